// round 16
// baseline (speedup 1.0000x reference)
#include <cuda_runtime.h>
#include <cuda_bf16.h>
#include <cuda_fp16.h>
#include <math.h>

// ---------------------------------------------------------------------------
// SCM: out = PWL( eps @ inv(I - A) )
//   eps: [B,16] f32, A: [16,16] f32, p: [16,101] f32, b: [16] f32
// Table per (dim, idx): half2{w, c}, c = delta_bias[spi] - sp*w -> out=fma(z,w,c)
// GEMV: packed fp32x2 FMA (FFMA2) vs 64-bit constant words.
// Index: fused packed round — ffma2(z, INV, MAGIC+50) rounds in the FMA;
//        clamp on raw float bits (monotonic), &0x7F extracts the bin.
// Global I/O: 256-bit vector loads/stores (sm_100+ v8.f32).
// ---------------------------------------------------------------------------

#define NP1 101
#define DIMS 16
#define VMIN_F (-5.0f)
#define INT_LEN_F (10.0f / 99.0f)
#define INV_INT_LEN_F (99.0f / 10.0f)
#define MAGIC_F 12582912.0f            // 1.5 * 2^23
#define MAGIC_BITS_LO 0x4B400000u      // bits of 12582912.0f  (idx = 0)
#define MAGIC_BITS_HI 0x4B400064u      // bits of 12583012.0f  (idx = 100)

__device__ float    g_M[DIMS * DIMS];
__device__ __half2  g_tab[DIMS * NP1];
__constant__ unsigned long long c_M2[DIMS * 8];

__device__ __forceinline__ unsigned long long ffma2(unsigned long long a,
                                                    unsigned long long b,
                                                    unsigned long long c) {
    unsigned long long d;
    asm("fma.rn.f32x2 %0, %1, %2, %3;" : "=l"(d) : "l"(a), "l"(b), "l"(c));
    return d;
}
__device__ __forceinline__ unsigned long long pack2(float x) {
    unsigned long long d;
    asm("mov.b64 %0, {%1, %1};" : "=l"(d) : "f"(x));
    return d;
}
__device__ __forceinline__ void unpack2(unsigned long long v, float& lo, float& hi) {
    asm("mov.b64 {%0, %1}, %2;" : "=f"(lo), "=f"(hi) : "l"(v));
}
__device__ __forceinline__ void unpack2u(unsigned long long v, unsigned& lo, unsigned& hi) {
    asm("mov.b64 {%0, %1}, %2;" : "=r"(lo), "=r"(hi) : "l"(v));
}

__device__ __forceinline__ void ldg256(const float* ptr, float* v) {
    asm("ld.global.cs.v8.f32 {%0,%1,%2,%3,%4,%5,%6,%7}, [%8];"
        : "=f"(v[0]), "=f"(v[1]), "=f"(v[2]), "=f"(v[3]),
          "=f"(v[4]), "=f"(v[5]), "=f"(v[6]), "=f"(v[7])
        : "l"(ptr));
}
__device__ __forceinline__ void stg256(float* ptr, const float* v) {
    asm volatile("st.global.cs.v8.f32 [%0], {%1,%2,%3,%4,%5,%6,%7,%8};"
        :: "l"(ptr),
           "f"(v[0]), "f"(v[1]), "f"(v[2]), "f"(v[3]),
           "f"(v[4]), "f"(v[5]), "f"(v[6]), "f"(v[7])
        : "memory");
}

// ---------------------------------------------------------------------------
// Prep: 1 block, 544 threads (17 warps), NO barriers.
//   warp 16: 16x16 Gauss-Jordan inverse, rows in registers, shuffle-only.
//   warps 0..15: PWL table for dim = warp id, register-only with lane halos.
// ---------------------------------------------------------------------------
__global__ void __launch_bounds__(544) prep_kernel(const float* __restrict__ A,
                                                   const float* __restrict__ p,
                                                   const float* __restrict__ b) {
    const int warp = threadIdx.x >> 5;
    const int lane = threadIdx.x & 31;
    const unsigned FULL = 0xffffffffu;

    if (warp == 16) {
        float a[32];
        const int r = lane;
#pragma unroll
        for (int c = 0; c < 16; ++c) {
            float Av = (r < 16) ? A[r * 16 + c] : 0.0f;
            a[c]      = (r == c ? 1.0f : 0.0f) - Av;
            a[16 + c] = (r == c ? 1.0f : 0.0f);
        }
#pragma unroll
        for (int col = 0; col < 16; ++col) {
            float v = (lane >= col && lane < 16) ? fabsf(a[col]) : -1.0f;
            int ix = lane;
#pragma unroll
            for (int o = 16; o > 0; o >>= 1) {
                float vo = __shfl_xor_sync(FULL, v, o);
                int   io = __shfl_xor_sync(FULL, ix, o);
                if (vo > v || (vo == v && io < ix)) { v = vo; ix = io; }
            }
            const int piv = ix;
            const int partner = (lane == col) ? piv : (lane == piv) ? col : lane;
#pragma unroll
            for (int k = 0; k < 32; ++k)
                a[k] = __shfl_sync(FULL, a[k], partner);
            const float pv  = __shfl_sync(FULL, a[col], col);
            const float inv = 1.0f / pv;
            const float fac = (lane == col) ? 0.0f : a[col];
#pragma unroll
            for (int k = 0; k < 32; ++k) {
                const float prs = __shfl_sync(FULL, a[k], col) * inv;
                a[k] = (lane == col) ? prs : fmaf(-fac, prs, a[k]);
            }
        }
        if (r < 16) {
#pragma unroll
            for (int c = 0; c < 16; ++c)
                g_M[r * 16 + c] = a[16 + c];
        }
    } else {
        const int d = warp;                 // one dim per warp
        const float* pd = p + d * NP1;

        float wl[4];
#pragma unroll
        for (int q = 0; q < 4; ++q) {
            const int i = 4 * lane + q;
            wl[q] = (i < NP1) ? (expf(pd[i]) + 0.001f) : 0.0f;
        }
        const float w_next0 = __shfl_down_sync(FULL, wl[0], 1);

        float pre[4];
        float loc = 0.0f;
#pragma unroll
        for (int q = 0; q < 4; ++q) {
            const int i = 4 * lane + q;
            const float wip1 = (q < 3) ? wl[q + 1] : w_next0;
            const float v = (i < 99) ? (INT_LEN_F * wip1) : 0.0f;
            loc += v;
            pre[q] = loc;
        }
        float tot = loc;
#pragma unroll
        for (int o = 1; o < 32; o <<= 1) {
            const float t = __shfl_up_sync(FULL, tot, o);
            if (lane >= o) tot += t;
        }
        const float excl = tot - loc;
        float S[4];
#pragma unroll
        for (int q = 0; q < 4; ++q)
            S[q] = excl + (q == 0 ? 0.0f : pre[q - 1]);
        const float S_prevlast = __shfl_up_sync(FULL, S[3], 1);

        const float bd = b[d];
#pragma unroll
        for (int q = 0; q < 4; ++q) {
            const int idx = 4 * lane + q;
            if (idx < NP1) {
                const int   spi = idx > 0 ? idx - 1 : 0;
                const float Ssp = (idx == 0) ? 0.0f
                                : (q == 0)   ? S_prevlast
                                             : S[q - 1];
                const float w  = wl[q];
                const float sp = fmaf((float)spi, INT_LEN_F, VMIN_F);
                const float db = bd + Ssp;
                g_tab[d * NP1 + idx] = __floats2half2_rn(w, fmaf(-sp, w, db));
            }
        }
    }
}

// ---------------------------------------------------------------------------
// Epilogue for 8 dims [J0, J0+8): fused packed-round index, batched gathers.
// ---------------------------------------------------------------------------
template<int J0>
__device__ __forceinline__ void pwl_batch8(const unsigned long long* z2,
                                           unsigned long long INV2,
                                           unsigned long long K2,
                                           const __half2* s_tab, float* o) {
    float zv[8];
    unsigned bi[8];
#pragma unroll
    for (int q = 0; q < 4; ++q) {
        unpack2(z2[J0 / 2 + q], zv[2 * q], zv[2 * q + 1]);
        // packed: round(z*INV + 50) via magic addend inside the FMA
        const unsigned long long y2 = ffma2(z2[J0 / 2 + q], INV2, K2);
        unpack2u(y2, bi[2 * q], bi[2 * q + 1]);
    }

    int ti[8];
#pragma unroll
    for (int q = 0; q < 8; ++q) {
        // clamp on raw bits (monotonic in this exponent range), extract bin
        unsigned m = umin(umax(bi[q], MAGIC_BITS_LO), MAGIC_BITS_HI);
        ti[q] = (int)(m & 0x7Fu);
    }
    __half2 u[8];
#pragma unroll
    for (int q = 0; q < 8; ++q) u[q] = s_tab[(J0 + q) * NP1 + ti[q]];
#pragma unroll
    for (int q = 0; q < 8; ++q) {
        const float2 wc = __half22float2(u[q]);
        o[J0 + q] = fmaf(zv[q], wc.x, wc.y);
    }
}

// ---------------------------------------------------------------------------
// Main kernel: persistent grid-stride, 1 row/thread/iter, 256-bit global I/O.
// ---------------------------------------------------------------------------
__global__ void __launch_bounds__(256) scm_main_kernel(const float* __restrict__ eps,
                                                       float* __restrict__ out,
                                                       int B, int stride) {
    __shared__ __half2 s_tab[DIMS * NP1];
    for (int i = threadIdx.x; i < DIMS * NP1; i += 256) s_tab[i] = g_tab[i];
    __syncthreads();

    const unsigned long long INV2 = pack2(INV_INT_LEN_F);
    const unsigned long long K2   = pack2(MAGIC_F + 50.0f);

    for (int row = blockIdx.x * 256 + threadIdx.x; row < B; row += stride) {
        const float* ep = eps + (size_t)row * 16;
        float e[16];
        ldg256(ep, e);
        ldg256(ep + 8, e + 8);

        unsigned long long z2[8];
#pragma unroll
        for (int j = 0; j < 8; ++j) z2[j] = 0ULL;

#pragma unroll
        for (int k = 0; k < 16; ++k) {
            const unsigned long long ek2 = pack2(e[k]);
#pragma unroll
            for (int j = 0; j < 8; ++j)
                z2[j] = ffma2(ek2, c_M2[k * 8 + j], z2[j]);
        }

        float o[16];
        pwl_batch8<0>(z2, INV2, K2, s_tab, o);
        pwl_batch8<8>(z2, INV2, K2, s_tab, o);

        float* op = out + (size_t)row * 16;
        stg256(op, o);
        stg256(op + 8, o + 8);
    }
}

// ---------------------------------------------------------------------------
extern "C" void kernel_launch(void* const* d_in, const int* in_sizes, int n_in,
                              void* d_out, int out_size) {
    const float* eps = nullptr;
    const float* A   = nullptr;
    const float* p   = nullptr;
    const float* b   = nullptr;
    int eps_elems = 0;
    for (int i = 0; i < n_in; ++i) {
        const int sz = in_sizes[i];
        if (sz == 256)       A = (const float*)d_in[i];
        else if (sz == 1616) p = (const float*)d_in[i];
        else if (sz == 16)   b = (const float*)d_in[i];
        else { eps = (const float*)d_in[i]; eps_elems = sz; }
    }
    const int B = eps_elems / 16;

    prep_kernel<<<1, 544>>>(A, p, b);

    void* gM_ptr = nullptr;
    cudaGetSymbolAddress(&gM_ptr, g_M);
    cudaMemcpyToSymbolAsync(c_M2, gM_ptr, DIMS * DIMS * sizeof(float), 0,
                            cudaMemcpyDeviceToDevice);

    int sm_count = 148;
    cudaDeviceGetAttribute(&sm_count, cudaDevAttrMultiProcessorCount, 0);
    int blocks_per_sm = 8;
    cudaOccupancyMaxActiveBlocksPerMultiprocessor(&blocks_per_sm, scm_main_kernel,
                                                  256, DIMS * NP1 * sizeof(__half2));
    if (blocks_per_sm < 1) blocks_per_sm = 1;
    const int blocks = sm_count * blocks_per_sm;
    const int stride = blocks * 256;
    scm_main_kernel<<<blocks, 256>>>((const float*)eps, (float*)d_out, B, stride);
}

// round 17
// speedup vs baseline: 1.2561x; 1.2561x over previous
#include <cuda_runtime.h>
#include <cuda_bf16.h>
#include <cuda_fp16.h>
#include <math.h>

// ---------------------------------------------------------------------------
// SCM: out = PWL( eps @ inv(I - A) )
//   eps: [B,16] f32, A: [16,16] f32, p: [16,101] f32, b: [16] f32
// Table per (dim, idx): half2{w, c}, c = delta_bias[spi] - sp*w -> out=fma(z,w,c)
// GEMV: packed fp32x2 FMA (FFMA2) vs 64-bit constant words.
// Global I/O: 256-bit vector loads/stores, DEFAULT cache policy (L2 reuse
// across graph replays: 126MB L2 vs 256MB working set).
// ---------------------------------------------------------------------------

#define NP1 101
#define DIMS 16
#define VMIN_F (-5.0f)
#define INT_LEN_F (10.0f / 99.0f)
#define INV_INT_LEN_F (99.0f / 10.0f)
#define MAGIC_F 12582912.0f   // 1.5 * 2^23

__device__ float    g_M[DIMS * DIMS];
__device__ __half2  g_tab[DIMS * NP1];
__constant__ unsigned long long c_M2[DIMS * 8];

__device__ __forceinline__ unsigned long long ffma2(unsigned long long a,
                                                    unsigned long long b,
                                                    unsigned long long c) {
    unsigned long long d;
    asm("fma.rn.f32x2 %0, %1, %2, %3;" : "=l"(d) : "l"(a), "l"(b), "l"(c));
    return d;
}
__device__ __forceinline__ unsigned long long pack2(float x) {
    unsigned long long d;
    asm("mov.b64 %0, {%1, %1};" : "=l"(d) : "f"(x));
    return d;
}
__device__ __forceinline__ void unpack2(unsigned long long v, float& lo, float& hi) {
    asm("mov.b64 {%0, %1}, %2;" : "=f"(lo), "=f"(hi) : "l"(v));
}

__device__ __forceinline__ void ldg256(const float* ptr, float* v) {
    asm("ld.global.v8.f32 {%0,%1,%2,%3,%4,%5,%6,%7}, [%8];"
        : "=f"(v[0]), "=f"(v[1]), "=f"(v[2]), "=f"(v[3]),
          "=f"(v[4]), "=f"(v[5]), "=f"(v[6]), "=f"(v[7])
        : "l"(ptr));
}
__device__ __forceinline__ void stg256(float* ptr, const float* v) {
    asm volatile("st.global.v8.f32 [%0], {%1,%2,%3,%4,%5,%6,%7,%8};"
        :: "l"(ptr),
           "f"(v[0]), "f"(v[1]), "f"(v[2]), "f"(v[3]),
           "f"(v[4]), "f"(v[5]), "f"(v[6]), "f"(v[7])
        : "memory");
}

// ---------------------------------------------------------------------------
// Prep: 1 block, 544 threads (17 warps), NO barriers.
//   warp 16: 16x16 Gauss-Jordan inverse, rows in registers, shuffle-only.
//   warps 0..15: PWL table for dim = warp id, register-only with lane halos.
// ---------------------------------------------------------------------------
__global__ void __launch_bounds__(544) prep_kernel(const float* __restrict__ A,
                                                   const float* __restrict__ p,
                                                   const float* __restrict__ b) {
    const int warp = threadIdx.x >> 5;
    const int lane = threadIdx.x & 31;
    const unsigned FULL = 0xffffffffu;

    if (warp == 16) {
        float a[32];
        const int r = lane;
#pragma unroll
        for (int c = 0; c < 16; ++c) {
            float Av = (r < 16) ? A[r * 16 + c] : 0.0f;
            a[c]      = (r == c ? 1.0f : 0.0f) - Av;
            a[16 + c] = (r == c ? 1.0f : 0.0f);
        }
#pragma unroll
        for (int col = 0; col < 16; ++col) {
            float v = (lane >= col && lane < 16) ? fabsf(a[col]) : -1.0f;
            int ix = lane;
#pragma unroll
            for (int o = 16; o > 0; o >>= 1) {
                float vo = __shfl_xor_sync(FULL, v, o);
                int   io = __shfl_xor_sync(FULL, ix, o);
                if (vo > v || (vo == v && io < ix)) { v = vo; ix = io; }
            }
            const int piv = ix;
            const int partner = (lane == col) ? piv : (lane == piv) ? col : lane;
#pragma unroll
            for (int k = 0; k < 32; ++k)
                a[k] = __shfl_sync(FULL, a[k], partner);
            const float pv  = __shfl_sync(FULL, a[col], col);
            const float inv = 1.0f / pv;
            const float fac = (lane == col) ? 0.0f : a[col];
#pragma unroll
            for (int k = 0; k < 32; ++k) {
                const float prs = __shfl_sync(FULL, a[k], col) * inv;
                a[k] = (lane == col) ? prs : fmaf(-fac, prs, a[k]);
            }
        }
        if (r < 16) {
#pragma unroll
            for (int c = 0; c < 16; ++c)
                g_M[r * 16 + c] = a[16 + c];
        }
    } else {
        const int d = warp;
        const float* pd = p + d * NP1;

        float wl[4];
#pragma unroll
        for (int q = 0; q < 4; ++q) {
            const int i = 4 * lane + q;
            wl[q] = (i < NP1) ? (expf(pd[i]) + 0.001f) : 0.0f;
        }
        const float w_next0 = __shfl_down_sync(FULL, wl[0], 1);

        float pre[4];
        float loc = 0.0f;
#pragma unroll
        for (int q = 0; q < 4; ++q) {
            const int i = 4 * lane + q;
            const float wip1 = (q < 3) ? wl[q + 1] : w_next0;
            const float v = (i < 99) ? (INT_LEN_F * wip1) : 0.0f;
            loc += v;
            pre[q] = loc;
        }
        float tot = loc;
#pragma unroll
        for (int o = 1; o < 32; o <<= 1) {
            const float t = __shfl_up_sync(FULL, tot, o);
            if (lane >= o) tot += t;
        }
        const float excl = tot - loc;
        float S[4];
#pragma unroll
        for (int q = 0; q < 4; ++q)
            S[q] = excl + (q == 0 ? 0.0f : pre[q - 1]);
        const float S_prevlast = __shfl_up_sync(FULL, S[3], 1);

        const float bd = b[d];
#pragma unroll
        for (int q = 0; q < 4; ++q) {
            const int idx = 4 * lane + q;
            if (idx < NP1) {
                const int   spi = idx > 0 ? idx - 1 : 0;
                const float Ssp = (idx == 0) ? 0.0f
                                : (q == 0)   ? S_prevlast
                                             : S[q - 1];
                const float w  = wl[q];
                const float sp = fmaf((float)spi, INT_LEN_F, VMIN_F);
                const float db = bd + Ssp;
                g_tab[d * NP1 + idx] = __floats2half2_rn(w, fmaf(-sp, w, db));
            }
        }
    }
}

// ---------------------------------------------------------------------------
// Epilogue for 8 dims [J0, J0+8): all-float index (FFMA-imm + FMNMX + magic
// add; per-dim table base folded into the FFMA constant), batched gathers.
// ---------------------------------------------------------------------------
template<int J0>
__device__ __forceinline__ void pwl_batch8(const unsigned long long* z2,
                                           const __half2* s_tab, float* o) {
    float zv[8];
#pragma unroll
    for (int q = 0; q < 4; ++q)
        unpack2(z2[J0 / 2 + q], zv[2 * q], zv[2 * q + 1]);

    int ti[8];
#pragma unroll
    for (int q = 0; q < 8; ++q) {
        const int j = J0 + q;
        const float base = 101.0f * (float)j;
        float y = fmaf(zv[q], INV_INT_LEN_F, 50.0f + base);
        y = fminf(y, base + 99.501f);
        y = fmaxf(y, base - 0.499f);
        const float m = y + MAGIC_F;
        ti[q] = __float_as_int(m) & 0x3FFFFF;
    }
    __half2 u[8];
#pragma unroll
    for (int q = 0; q < 8; ++q) u[q] = s_tab[ti[q]];
#pragma unroll
    for (int q = 0; q < 8; ++q) {
        const float2 wc = __half22float2(u[q]);
        o[J0 + q] = fmaf(zv[q], wc.x, wc.y);
    }
}

// ---------------------------------------------------------------------------
// Main kernel: persistent grid-stride, 1 row/thread/iter, 256-bit global I/O.
// ---------------------------------------------------------------------------
__global__ void __launch_bounds__(256) scm_main_kernel(const float* __restrict__ eps,
                                                       float* __restrict__ out,
                                                       int B, int stride) {
    __shared__ __half2 s_tab[DIMS * NP1];
    for (int i = threadIdx.x; i < DIMS * NP1; i += 256) s_tab[i] = g_tab[i];
    __syncthreads();

    for (int row = blockIdx.x * 256 + threadIdx.x; row < B; row += stride) {
        const float* ep = eps + (size_t)row * 16;
        float e[16];
        ldg256(ep, e);
        ldg256(ep + 8, e + 8);

        unsigned long long z2[8];
#pragma unroll
        for (int j = 0; j < 8; ++j) z2[j] = 0ULL;

#pragma unroll
        for (int k = 0; k < 16; ++k) {
            const unsigned long long ek2 = pack2(e[k]);
#pragma unroll
            for (int j = 0; j < 8; ++j)
                z2[j] = ffma2(ek2, c_M2[k * 8 + j], z2[j]);
        }

        float o[16];
        pwl_batch8<0>(z2, s_tab, o);
        pwl_batch8<8>(z2, s_tab, o);

        float* op = out + (size_t)row * 16;
        stg256(op, o);
        stg256(op + 8, o + 8);
    }
}

// ---------------------------------------------------------------------------
extern "C" void kernel_launch(void* const* d_in, const int* in_sizes, int n_in,
                              void* d_out, int out_size) {
    const float* eps = nullptr;
    const float* A   = nullptr;
    const float* p   = nullptr;
    const float* b   = nullptr;
    int eps_elems = 0;
    for (int i = 0; i < n_in; ++i) {
        const int sz = in_sizes[i];
        if (sz == 256)       A = (const float*)d_in[i];
        else if (sz == 1616) p = (const float*)d_in[i];
        else if (sz == 16)   b = (const float*)d_in[i];
        else { eps = (const float*)d_in[i]; eps_elems = sz; }
    }
    const int B = eps_elems / 16;

    prep_kernel<<<1, 544>>>(A, p, b);

    void* gM_ptr = nullptr;
    cudaGetSymbolAddress(&gM_ptr, g_M);
    cudaMemcpyToSymbolAsync(c_M2, gM_ptr, DIMS * DIMS * sizeof(float), 0,
                            cudaMemcpyDeviceToDevice);

    int sm_count = 148;
    cudaDeviceGetAttribute(&sm_count, cudaDevAttrMultiProcessorCount, 0);
    int blocks_per_sm = 8;
    cudaOccupancyMaxActiveBlocksPerMultiprocessor(&blocks_per_sm, scm_main_kernel,
                                                  256, DIMS * NP1 * sizeof(__half2));
    if (blocks_per_sm < 1) blocks_per_sm = 1;
    const int blocks = sm_count * blocks_per_sm;
    const int stride = blocks * 256;
    scm_main_kernel<<<blocks, 256>>>((const float*)eps, (float*)d_out, B, stride);
}